// round 9
// baseline (speedup 1.0000x reference)
#include <cuda_runtime.h>

// ---------------- problem constants ----------------
#define B_SZ   4
#define C_IN   32
#define C_OUT  32
#define HW_DIM 256
#define PLANE  (HW_DIM * HW_DIM)   // 65536
#define KTAPS  9

// conv tile: 64 cols x 8 rows per block, 256 threads = 8 warps (1 row/warp)
// cin in 4 passes of 8 channels; u staged via cp.async double buffer
#define TW 64
#define TH 8
#define IW 66
#define IH 10
#define POS (IH * IW)              // 660 halo positions
#define NTHREADS 256
#define NPASS 4
#define PPAD 8                     // floats per position (8 cin, permuted slots)

#define SU_FLOATS (POS * PPAD)            // 5280 per buffer
#define SWF_FLOATS (36 * 4 * 64)          // 9216 B fragments
#define SB_FLOATS 32
#define SMEM_FLOATS (2 * SU_FLOATS + SWF_FLOATS + SB_FLOATS)  // 19808
#define SMEM_BYTES  (SMEM_FLOATS * 4)     // 79232 B -> 2 blocks/SM
// epilogue vout overlay: 8*32*65 = 16640 floats < 2*SU+SWF ok (sb untouched)

// scratch: pre-scaled tf32 u field, NHWC8 slot-permuted: [b][pass][pixel][8]
__device__ float g_U[(size_t)B_SZ * NPASS * PLANE * 8];   // 33.5 MB

// ---------------- helpers ----------------
__device__ __forceinline__ unsigned to_tf32(float x) {
    unsigned r;
    asm("cvt.rna.tf32.f32 %0, %1;" : "=r"(r) : "f"(x));
    return r;
}
__device__ __forceinline__ float tf32f(float x) { return __uint_as_float(to_tf32(x)); }

__device__ __forceinline__ void mma_tf32(float* c,
                                         unsigned a0, unsigned a1,
                                         unsigned a2, unsigned a3,
                                         unsigned b0, unsigned b1) {
    asm("mma.sync.aligned.m16n8k8.row.col.f32.tf32.tf32.f32 "
        "{%0,%1,%2,%3},{%4,%5,%6,%7},{%8,%9},{%0,%1,%2,%3};"
        : "+f"(c[0]), "+f"(c[1]), "+f"(c[2]), "+f"(c[3])
        : "r"(a0), "r"(a1), "r"(a2), "r"(a3), "r"(b0), "r"(b1));
}

__device__ __forceinline__ void cp16(unsigned smem_addr, const void* gptr, int src_sz) {
    asm volatile("cp.async.ca.shared.global [%0], [%1], 16, %2;"
                 :: "r"(smem_addr), "l"(gptr), "r"(src_sz));
}
__device__ __forceinline__ unsigned smem_u32(const void* p) {
    return (unsigned)__cvta_generic_to_shared(p);
}

// ---------------- kernel 1: log0 scale + pre-scaled permuted tf32 field ----
__global__ void log0_scale_kernel(const float* __restrict__ x) {
    int pid = blockIdx.x * blockDim.x + threadIdx.x;   // 0 .. B*PLANE-1
    int b = pid >> 16;
    int p = pid & (PLANE - 1);
    const float* xb = x + ((size_t)b * C_IN) * PLANE + p;
    float v[C_IN];
    float ss = 0.f;
#pragma unroll
    for (int c = 0; c < C_IN; c++) {
        v[c] = xb[(size_t)c * PLANE];
        ss += v[c] * v[c];
    }
    float n = fmaxf(sqrtf(ss), 1e-7f);
    float a = fminf(0.1f * n, 1.0f - 1e-6f);
    float S = atanhf(a) / (0.1f * n);

#pragma unroll
    for (int pass = 0; pass < NPASS; pass++) {
        const float* u = v + pass * 8;
        float4 lo, hi;   // slot(c) = 2*(c&3) + (c>>2)
        lo.x = tf32f(S * u[0]); lo.y = tf32f(S * u[4]);
        lo.z = tf32f(S * u[1]); lo.w = tf32f(S * u[5]);
        hi.x = tf32f(S * u[2]); hi.y = tf32f(S * u[6]);
        hi.z = tf32f(S * u[3]); hi.w = tf32f(S * u[7]);
        float4* go = (float4*)(g_U + ((((size_t)(b * NPASS + pass)) << 16) + p) * 8);
        go[0] = lo;
        go[1] = hi;
    }
}

// ---------------- kernel 2: tf32 mma implicit-GEMM conv + bias + relu + exp0 ----
__global__ __launch_bounds__(NTHREADS, 2)
void pvconv_kernel(const float* __restrict__ Wk,
                   const float* __restrict__ bias,
                   float* __restrict__ out) {
    extern __shared__ float sm[];
    float* su0 = sm;                       // [POS][8] pass buffer 0
    float* su1 = sm + SU_FLOATS;           // pass buffer 1
    float* swf = sm + 2 * SU_FLOATS;       // B fragments [ks][n8][lane][2]
    float* sb  = swf + SWF_FLOATS;         // [32] bias

    const int tid = threadIdx.x;
    const int b  = blockIdx.z;
    const int r0 = blockIdx.y * TH;
    const int c0 = blockIdx.x * TW;
    const int lane = tid & 31;
    const int warp = tid >> 5;             // output row within tile (0..7)

    // --- stage B fragments (tf32) + bias ---
    for (int fidx = tid; fidx < SWF_FLOATS; fidx += NTHREADS) {
        int reg  = fidx & 1;
        int pair = fidx >> 1;
        int ls   = pair & 31;
        int n8ks = pair >> 5;
        int n8   = n8ks & 3;
        int ks   = n8ks >> 2;
        int tap  = ks >> 2;
        int cc4  = ks & 3;                         // = pass index
        int cin  = cc4 * 8 + (ls & 3) + 4 * reg;   // B row (k)
        int cout = n8 * 8 + (ls >> 2);             // B col (n)
        swf[fidx] = tf32f(Wk[tap * 1024 + cout * 32 + cin]);
    }
    if (tid < 32) sb[tid] = bias[tid];

    // --- precompute this thread's halo positions (<=3) ---
    int myN = 0;
    size_t goff[3];     // pixel*8 (float offset within a pass plane)
    unsigned sdst[3];   // smem byte addr within su0
    int      szs[3];    // 16 or 0 (zfill OOB)
#pragma unroll
    for (int i = 0; i < 3; i++) {
        int p = tid + i * NTHREADS;
        if (p < POS) {
            int rr = p / IW;
            int cc = p - rr * IW;
            int gh = r0 - 1 + rr, gw = c0 - 1 + cc;
            bool ok = (unsigned)gh < (unsigned)HW_DIM && (unsigned)gw < (unsigned)HW_DIM;
            goff[i] = ok ? (size_t)((gh << 8) + gw) * 8 : 0;
            sdst[i] = smem_u32(su0 + p * PPAD);
            szs[i]  = ok ? 16 : 0;
            myN = i + 1;
        }
    }
    const unsigned bufo = SU_FLOATS * 4;   // byte offset between buffers

    // --- stage pass 0 ---
    {
        const float* gsrc = g_U + (((size_t)(b * NPASS)) << 16) * 8;
#pragma unroll
        for (int i = 0; i < 3; i++)
            if (i < myN) {
                cp16(sdst[i],      gsrc + goff[i],     szs[i]);
                cp16(sdst[i] + 16, gsrc + goff[i] + 4, szs[i]);
            }
        asm volatile("cp.async.commit_group;");
    }

    float acc[4][4][4];                    // [g16][n8][reg]
#pragma unroll
    for (int g = 0; g < 4; g++)
#pragma unroll
        for (int n = 0; n < 4; n++)
#pragma unroll
            for (int r = 0; r < 4; r++) acc[g][n][r] = 0.f;

    const int q = lane >> 2;               // 0..7: pixel-col-within-m16
    const int t = lane & 3;                // 0..3: k-within-chunk

#pragma unroll 1
    for (int pass = 0; pass < NPASS; pass++) {
        // prefetch next pass into the other buffer
        if (pass + 1 < NPASS) {
            const float* gsrc = g_U + (((size_t)(b * NPASS + pass + 1)) << 16) * 8;
            unsigned dof = ((pass + 1) & 1) * bufo;
#pragma unroll
            for (int i = 0; i < 3; i++)
                if (i < myN) {
                    cp16(sdst[i] + dof,      gsrc + goff[i],     szs[i]);
                    cp16(sdst[i] + dof + 16, gsrc + goff[i] + 4, szs[i]);
                }
            asm volatile("cp.async.commit_group;");
            asm volatile("cp.async.wait_group 1;");
        } else {
            asm volatile("cp.async.wait_group 0;");
        }
        __syncthreads();    // buf[pass] data visible to all warps

        const float2* supos = (const float2*)((pass & 1) ? su1 : su0);
        // per-pass base pointers (compile-time tap offsets after unroll)
        const float2* abase = supos + (warp * IW + q) * (PPAD / 2) + t;
        const float2* bbase = (const float2*)swf + (size_t)pass * 128 + lane;

        // --- mma: 9 taps FULLY UNROLLED (ILP: next-tap LDS under current MMAs)
#pragma unroll
        for (int tap = 0; tap < KTAPS; tap++) {
            const int ki = tap / 3;
            const int kj = tap - ki * 3;
            // B prefetch (4 x LDS.64, immediate offsets)
            const float2* bp = bbase + (size_t)tap * 512;
            float2 bfr[4];
#pragma unroll
            for (int n8 = 0; n8 < 4; n8++) bfr[n8] = bp[n8 * 32];

            // A fragments: 8 x LDS.64, conflict-free, immediate offsets
            const float2* ap = abase + (ki * IW + kj) * (PPAD / 2);
            unsigned a[4][4];
#pragma unroll
            for (int g = 0; g < 4; g++) {
                float2 lo = ap[g * 16 * (PPAD / 2)];            // row g*16+q
                float2 hi = ap[(g * 16 + 8) * (PPAD / 2)];      // row g*16+q+8
                a[g][0] = __float_as_uint(lo.x);   // k=t
                a[g][2] = __float_as_uint(lo.y);   // k=t+4
                a[g][1] = __float_as_uint(hi.x);
                a[g][3] = __float_as_uint(hi.y);
            }
#pragma unroll
            for (int n8 = 0; n8 < 4; n8++) {
                unsigned b0 = __float_as_uint(bfr[n8].x);
                unsigned b1 = __float_as_uint(bfr[n8].y);
#pragma unroll
                for (int g = 0; g < 4; g++)
                    mma_tf32(acc[g][n8], a[g][0], a[g][1], a[g][2], a[g][3], b0, b1);
            }
        }
        __syncthreads();    // all warps done reading buf[pass] (restaged at pass+2)
    }

    // bias pairs (preload before vout overlay)
    float2 bfrag[4];
#pragma unroll
    for (int n8 = 0; n8 < 4; n8++) bfrag[n8] = ((const float2*)sb)[n8 * 4 + t];

    // --- epilogue: bias + relu + exp0 (4-lane butterfly for the cout norm) ---
    float* vout = sm + warp * (C_OUT * 65);   // [cout][65] per-warp staging
#pragma unroll
    for (int g = 0; g < 4; g++) {
        float s0 = 0.f, s1 = 0.f;
#pragma unroll
        for (int n8 = 0; n8 < 4; n8++) {
            float2 bb = bfrag[n8];
            float v0 = fmaxf(acc[g][n8][0] + bb.x, 0.f);
            float v1 = fmaxf(acc[g][n8][1] + bb.y, 0.f);
            float v2 = fmaxf(acc[g][n8][2] + bb.x, 0.f);
            float v3 = fmaxf(acc[g][n8][3] + bb.y, 0.f);
            s0 += v0 * v0 + v1 * v1;
            s1 += v2 * v2 + v3 * v3;
            acc[g][n8][0] = v0; acc[g][n8][1] = v1;
            acc[g][n8][2] = v2; acc[g][n8][3] = v3;
        }
        s0 += __shfl_xor_sync(0xffffffffu, s0, 1);
        s0 += __shfl_xor_sync(0xffffffffu, s0, 2);
        s1 += __shfl_xor_sync(0xffffffffu, s1, 1);
        s1 += __shfl_xor_sync(0xffffffffu, s1, 2);
        float n0 = fmaxf(sqrtf(s0), 1e-7f);
        float n1 = fmaxf(sqrtf(s1), 1e-7f);
        float f0 = tanhf(0.1f * n0) / (0.1f * n0);
        float f1 = tanhf(0.1f * n1) / (0.1f * n1);
        const int colA = g * 16 + q;
        const int colB = colA + 8;
#pragma unroll
        for (int n8 = 0; n8 < 4; n8++) {
            int cbase = n8 * 8 + 2 * t;
            vout[cbase * 65 + colA]       = f0 * acc[g][n8][0];
            vout[(cbase + 1) * 65 + colA] = f0 * acc[g][n8][1];
            vout[cbase * 65 + colB]       = f1 * acc[g][n8][2];
            vout[(cbase + 1) * 65 + colB] = f1 * acc[g][n8][3];
        }
    }
    __syncwarp();

    // --- coalesced stores: warp copies its row, all 32 couts ---
    {
        float* outb = out + (((size_t)b * C_OUT) << 16) + ((r0 + warp) << 8) + c0;
#pragma unroll 4
        for (int j = 0; j < 64; j++) {
            int c = j >> 1;
            int half = j & 1;
            float v = vout[c * 65 + lane + (half << 5)];
            outb[((size_t)c << 16) + lane + (half << 5)] = v;
        }
    }
}

// ---------------- launch ----------------
extern "C" void kernel_launch(void* const* d_in, const int* in_sizes, int n_in,
                              void* d_out, int out_size) {
    const float* x    = (const float*)d_in[0];
    const float* Wk   = (const float*)d_in[1];
    const float* bias = (const float*)d_in[2];
    float* out = (float*)d_out;

    cudaFuncSetAttribute(pvconv_kernel,
                         cudaFuncAttributeMaxDynamicSharedMemorySize, SMEM_BYTES);

    // kernel 1: per-pixel log0 scale + pre-scaled permuted tf32 field
    log0_scale_kernel<<<(B_SZ * PLANE) / 256, 256>>>(x);

    // kernel 2: tf32 tensor-core conv + bias + relu + exp0
    dim3 grid(HW_DIM / TW, HW_DIM / TH, B_SZ);   // (4, 32, 4) = 512 blocks
    pvconv_kernel<<<grid, NTHREADS, SMEM_BYTES>>>(Wk, bias, out);
}

// round 10
// speedup vs baseline: 1.0043x; 1.0043x over previous
#include <cuda_runtime.h>

// ---------------- problem constants ----------------
#define B_SZ   4
#define C_IN   32
#define C_OUT  32
#define HW_DIM 256
#define PLANE  (HW_DIM * HW_DIM)   // 65536
#define KTAPS  9

// conv tile: 64 cols x 8 rows per block, 256 threads = 8 warps (1 row/warp)
// cin in 4 passes of 8 channels; u staged via cp.async double buffer
#define TW 64
#define TH 8
#define IW 66
#define IH 10
#define POS (IH * IW)              // 660 halo positions
#define NTHREADS 256
#define NPASS 4
#define PPAD 8                     // floats per position (8 cin, permuted slots)

#define SU_FLOATS (POS * PPAD)            // 5280 per buffer
#define SWF_FLOATS (36 * 4 * 64)          // 9216 B fragments
#define SB_FLOATS 32
#define SMEM_FLOATS (2 * SU_FLOATS + SWF_FLOATS + SB_FLOATS)  // 19808
#define SMEM_BYTES  (SMEM_FLOATS * 4)     // 79232 B -> 2 blocks/SM
// epilogue vout overlay: 8*32*65 = 16640 floats < 2*SU+SWF ok (sb untouched)

// scratch: pre-scaled tf32 u field, NHWC8 slot-permuted: [b][pass][pixel][8]
__device__ float g_U[(size_t)B_SZ * NPASS * PLANE * 8];   // 33.5 MB

// ---------------- helpers ----------------
__device__ __forceinline__ unsigned to_tf32(float x) {
    unsigned r;
    asm("cvt.rna.tf32.f32 %0, %1;" : "=r"(r) : "f"(x));
    return r;
}
__device__ __forceinline__ float tf32f(float x) { return __uint_as_float(to_tf32(x)); }

__device__ __forceinline__ void mma_tf32(float* c,
                                         unsigned a0, unsigned a1,
                                         unsigned a2, unsigned a3,
                                         unsigned b0, unsigned b1) {
    asm("mma.sync.aligned.m16n8k8.row.col.f32.tf32.tf32.f32 "
        "{%0,%1,%2,%3},{%4,%5,%6,%7},{%8,%9},{%0,%1,%2,%3};"
        : "+f"(c[0]), "+f"(c[1]), "+f"(c[2]), "+f"(c[3])
        : "r"(a0), "r"(a1), "r"(a2), "r"(a3), "r"(b0), "r"(b1));
}

__device__ __forceinline__ void cp16(unsigned smem_addr, const void* gptr, int src_sz) {
    asm volatile("cp.async.ca.shared.global [%0], [%1], 16, %2;"
                 :: "r"(smem_addr), "l"(gptr), "r"(src_sz));
}
__device__ __forceinline__ unsigned smem_u32(const void* p) {
    return (unsigned)__cvta_generic_to_shared(p);
}

// ---------------- kernel 1: log0 scale + pre-scaled permuted tf32 field ----
__global__ void log0_scale_kernel(const float* __restrict__ x) {
    int pid = blockIdx.x * blockDim.x + threadIdx.x;   // 0 .. B*PLANE-1
    int b = pid >> 16;
    int p = pid & (PLANE - 1);
    const float* xb = x + ((size_t)b * C_IN) * PLANE + p;
    float v[C_IN];
    float ss = 0.f;
#pragma unroll
    for (int c = 0; c < C_IN; c++) {
        v[c] = xb[(size_t)c * PLANE];
        ss += v[c] * v[c];
    }
    float n = fmaxf(sqrtf(ss), 1e-7f);
    float a = fminf(0.1f * n, 1.0f - 1e-6f);
    float S = atanhf(a) / (0.1f * n);

#pragma unroll
    for (int pass = 0; pass < NPASS; pass++) {
        const float* u = v + pass * 8;
        float4 lo, hi;   // slot(c) = 2*(c&3) + (c>>2)
        lo.x = tf32f(S * u[0]); lo.y = tf32f(S * u[4]);
        lo.z = tf32f(S * u[1]); lo.w = tf32f(S * u[5]);
        hi.x = tf32f(S * u[2]); hi.y = tf32f(S * u[6]);
        hi.z = tf32f(S * u[3]); hi.w = tf32f(S * u[7]);
        float4* go = (float4*)(g_U + ((((size_t)(b * NPASS + pass)) << 16) + p) * 8);
        go[0] = lo;
        go[1] = hi;
    }
}

// ---------------- kernel 2: tf32 mma implicit-GEMM conv + bias + relu + exp0 ----
__global__ __launch_bounds__(NTHREADS, 2)
void pvconv_kernel(const float* __restrict__ Wk,
                   const float* __restrict__ bias,
                   float* __restrict__ out) {
    extern __shared__ float sm[];
    float* su0 = sm;                       // [POS][8] pass buffer 0
    float* su1 = sm + SU_FLOATS;           // pass buffer 1
    float* swf = sm + 2 * SU_FLOATS;       // B fragments [ks][n8][lane][2]
    float* sb  = swf + SWF_FLOATS;         // [32] bias

    const int tid = threadIdx.x;
    const int b  = blockIdx.z;
    const int r0 = blockIdx.y * TH;
    const int c0 = blockIdx.x * TW;
    const int lane = tid & 31;
    const int warp = tid >> 5;             // output row within tile (0..7)

    // --- stage B fragments (tf32) + bias ---
    for (int fidx = tid; fidx < SWF_FLOATS; fidx += NTHREADS) {
        int reg  = fidx & 1;
        int pair = fidx >> 1;
        int ls   = pair & 31;
        int n8ks = pair >> 5;
        int n8   = n8ks & 3;
        int ks   = n8ks >> 2;
        int tap  = ks >> 2;
        int cc4  = ks & 3;                         // = pass index
        int cin  = cc4 * 8 + (ls & 3) + 4 * reg;   // B row (k)
        int cout = n8 * 8 + (ls >> 2);             // B col (n)
        swf[fidx] = tf32f(Wk[tap * 1024 + cout * 32 + cin]);
    }
    if (tid < 32) sb[tid] = bias[tid];

    // --- precompute this thread's halo positions (<=3) ---
    int myN = 0;
    size_t goff[3];     // pixel*8 (float offset within a pass plane)
    unsigned sdst[3];   // smem byte addr within su0
    int      szs[3];    // 16 or 0 (zfill OOB)
#pragma unroll
    for (int i = 0; i < 3; i++) {
        int p = tid + i * NTHREADS;
        if (p < POS) {
            int rr = p / IW;
            int cc = p - rr * IW;
            int gh = r0 - 1 + rr, gw = c0 - 1 + cc;
            bool ok = (unsigned)gh < (unsigned)HW_DIM && (unsigned)gw < (unsigned)HW_DIM;
            goff[i] = ok ? (size_t)((gh << 8) + gw) * 8 : 0;
            sdst[i] = smem_u32(su0 + p * PPAD);
            szs[i]  = ok ? 16 : 0;
            myN = i + 1;
        }
    }
    const unsigned bufo = SU_FLOATS * 4;   // byte offset between buffers

    // --- stage pass 0 ---
    {
        const float* gsrc = g_U + (((size_t)(b * NPASS)) << 16) * 8;
#pragma unroll
        for (int i = 0; i < 3; i++)
            if (i < myN) {
                cp16(sdst[i],      gsrc + goff[i],     szs[i]);
                cp16(sdst[i] + 16, gsrc + goff[i] + 4, szs[i]);
            }
        asm volatile("cp.async.commit_group;");
    }

    float acc[4][4][4];                    // [g16][n8][reg]
#pragma unroll
    for (int g = 0; g < 4; g++)
#pragma unroll
        for (int n = 0; n < 4; n++)
#pragma unroll
            for (int r = 0; r < 4; r++) acc[g][n][r] = 0.f;

    const int q = lane >> 2;               // 0..7: pixel-col-within-m16
    const int t = lane & 3;                // 0..3: k-within-chunk

#pragma unroll 1
    for (int pass = 0; pass < NPASS; pass++) {
        // prefetch next pass into the other buffer
        if (pass + 1 < NPASS) {
            const float* gsrc = g_U + (((size_t)(b * NPASS + pass + 1)) << 16) * 8;
            unsigned dof = ((pass + 1) & 1) * bufo;
#pragma unroll
            for (int i = 0; i < 3; i++)
                if (i < myN) {
                    cp16(sdst[i] + dof,      gsrc + goff[i],     szs[i]);
                    cp16(sdst[i] + dof + 16, gsrc + goff[i] + 4, szs[i]);
                }
            asm volatile("cp.async.commit_group;");
            asm volatile("cp.async.wait_group 1;");
        } else {
            asm volatile("cp.async.wait_group 0;");
        }
        __syncthreads();    // buf[pass] data visible to all warps

        const float2* supos = (const float2*)((pass & 1) ? su1 : su0);
        // per-pass base pointers (compile-time tap offsets after unroll)
        const float2* abase = supos + (warp * IW + q) * (PPAD / 2) + t;
        const float2* bbase = (const float2*)swf + (size_t)pass * 128 + lane;

        // --- mma: 9 taps FULLY UNROLLED (ILP: next-tap LDS under current MMAs)
#pragma unroll
        for (int tap = 0; tap < KTAPS; tap++) {
            const int ki = tap / 3;
            const int kj = tap - ki * 3;
            // B prefetch (4 x LDS.64, immediate offsets)
            const float2* bp = bbase + (size_t)tap * 512;
            float2 bfr[4];
#pragma unroll
            for (int n8 = 0; n8 < 4; n8++) bfr[n8] = bp[n8 * 32];

            // A fragments: 8 x LDS.64, conflict-free, immediate offsets
            const float2* ap = abase + (ki * IW + kj) * (PPAD / 2);
            unsigned a[4][4];
#pragma unroll
            for (int g = 0; g < 4; g++) {
                float2 lo = ap[g * 16 * (PPAD / 2)];            // row g*16+q
                float2 hi = ap[(g * 16 + 8) * (PPAD / 2)];      // row g*16+q+8
                a[g][0] = __float_as_uint(lo.x);   // k=t
                a[g][2] = __float_as_uint(lo.y);   // k=t+4
                a[g][1] = __float_as_uint(hi.x);
                a[g][3] = __float_as_uint(hi.y);
            }
#pragma unroll
            for (int n8 = 0; n8 < 4; n8++) {
                unsigned b0 = __float_as_uint(bfr[n8].x);
                unsigned b1 = __float_as_uint(bfr[n8].y);
#pragma unroll
                for (int g = 0; g < 4; g++)
                    mma_tf32(acc[g][n8], a[g][0], a[g][1], a[g][2], a[g][3], b0, b1);
            }
        }
        __syncthreads();    // all warps done reading buf[pass] (restaged at pass+2)
    }

    // bias pairs (preload before vout overlay)
    float2 bfrag[4];
#pragma unroll
    for (int n8 = 0; n8 < 4; n8++) bfrag[n8] = ((const float2*)sb)[n8 * 4 + t];

    // --- epilogue: bias + relu + exp0 (4-lane butterfly for the cout norm) ---
    float* vout = sm + warp * (C_OUT * 65);   // [cout][65] per-warp staging
#pragma unroll
    for (int g = 0; g < 4; g++) {
        float s0 = 0.f, s1 = 0.f;
#pragma unroll
        for (int n8 = 0; n8 < 4; n8++) {
            float2 bb = bfrag[n8];
            float v0 = fmaxf(acc[g][n8][0] + bb.x, 0.f);
            float v1 = fmaxf(acc[g][n8][1] + bb.y, 0.f);
            float v2 = fmaxf(acc[g][n8][2] + bb.x, 0.f);
            float v3 = fmaxf(acc[g][n8][3] + bb.y, 0.f);
            s0 += v0 * v0 + v1 * v1;
            s1 += v2 * v2 + v3 * v3;
            acc[g][n8][0] = v0; acc[g][n8][1] = v1;
            acc[g][n8][2] = v2; acc[g][n8][3] = v3;
        }
        s0 += __shfl_xor_sync(0xffffffffu, s0, 1);
        s0 += __shfl_xor_sync(0xffffffffu, s0, 2);
        s1 += __shfl_xor_sync(0xffffffffu, s1, 1);
        s1 += __shfl_xor_sync(0xffffffffu, s1, 2);
        float n0 = fmaxf(sqrtf(s0), 1e-7f);
        float n1 = fmaxf(sqrtf(s1), 1e-7f);
        float f0 = tanhf(0.1f * n0) / (0.1f * n0);
        float f1 = tanhf(0.1f * n1) / (0.1f * n1);
        const int colA = g * 16 + q;
        const int colB = colA + 8;
#pragma unroll
        for (int n8 = 0; n8 < 4; n8++) {
            int cbase = n8 * 8 + 2 * t;
            vout[cbase * 65 + colA]       = f0 * acc[g][n8][0];
            vout[(cbase + 1) * 65 + colA] = f0 * acc[g][n8][1];
            vout[cbase * 65 + colB]       = f1 * acc[g][n8][2];
            vout[(cbase + 1) * 65 + colB] = f1 * acc[g][n8][3];
        }
    }
    __syncwarp();

    // --- coalesced stores: warp copies its row, all 32 couts ---
    {
        float* outb = out + (((size_t)b * C_OUT) << 16) + ((r0 + warp) << 8) + c0;
#pragma unroll 4
        for (int j = 0; j < 64; j++) {
            int c = j >> 1;
            int half = j & 1;
            float v = vout[c * 65 + lane + (half << 5)];
            outb[((size_t)c << 16) + lane + (half << 5)] = v;
        }
    }
}

// ---------------- launch ----------------
extern "C" void kernel_launch(void* const* d_in, const int* in_sizes, int n_in,
                              void* d_out, int out_size) {
    const float* x    = (const float*)d_in[0];
    const float* Wk   = (const float*)d_in[1];
    const float* bias = (const float*)d_in[2];
    float* out = (float*)d_out;

    cudaFuncSetAttribute(pvconv_kernel,
                         cudaFuncAttributeMaxDynamicSharedMemorySize, SMEM_BYTES);

    // kernel 1: per-pixel log0 scale + pre-scaled permuted tf32 field
    log0_scale_kernel<<<(B_SZ * PLANE) / 256, 256>>>(x);

    // kernel 2: tf32 tensor-core conv + bias + relu + exp0
    dim3 grid(HW_DIM / TW, HW_DIM / TH, B_SZ);   // (4, 32, 4) = 512 blocks
    pvconv_kernel<<<grid, NTHREADS, SMEM_BYTES>>>(Wk, bias, out);
}

// round 12
// speedup vs baseline: 1.4498x; 1.4437x over previous
#include <cuda_runtime.h>
#include <cuda_fp16.h>
#include <cstdint>

// ---------------- problem constants ----------------
#define B_SZ   4
#define C_IN   32
#define C_OUT  32
#define HW_DIM 256
#define PLANE  (HW_DIM * HW_DIM)
#define KTAPS  9

// conv tile: 64 cols x 8 rows per block, 256 threads = 8 warps (1 row/warp)
// all 32 cin resident in smem as fp16 -> no pass loop
#define TW 64
#define TH 8
#define IW 66
#define IH 10
#define POS (IH * IW)              // 660
#define NTHREADS 256
#define PBYTES 96                  // 64 data bytes + 32 pad (conflict-free LDS.64)

#define SU_BYTES   (POS * PBYTES)          // 63360
#define SWF_OFF    SU_BYTES                // B frags: 18 chunks x 4 n8 x 32 lanes x 8B
#define SWF_BYTES  (18 * 4 * 32 * 8)       // 18432
#define SBIAS_OFF  (SWF_OFF + SWF_BYTES)   // 81792
#define SMEM_BYTES (SBIAS_OFF + 128)       // 81920 -> 2 blocks/SM
// epilogue vout overlay: 8 warps * 32*65 floats = 66560 B < SBIAS_OFF (bias safe)

// pre-scaled fp16 u field, NHWC32, within-pixel half order per k16 chunk:
// [0,1,8,9, 2,3,10,11, 4,5,12,13, 6,7,14,15] (so thread t LDS.64 = k{2t,2t+1,2t+8,2t+9})
__device__ __half g_Uh[(size_t)B_SZ * PLANE * 32];   // 16.8 MB

// ---------------- helpers ----------------
__device__ __forceinline__ unsigned su32(const void* p) {
    return (unsigned)__cvta_generic_to_shared(p);
}
__device__ __forceinline__ void cp16(unsigned d, const void* s, int sz) {
    asm volatile("cp.async.ca.shared.global [%0], [%1], 16, %2;" :: "r"(d), "l"(s), "r"(sz));
}
__device__ __forceinline__ void mma_f16(float* c, unsigned a0, unsigned a1,
                                        unsigned a2, unsigned a3,
                                        unsigned b0, unsigned b1) {
    asm("mma.sync.aligned.m16n8k16.row.col.f32.f16.f16.f32 "
        "{%0,%1,%2,%3},{%4,%5,%6,%7},{%8,%9},{%0,%1,%2,%3};"
        : "+f"(c[0]), "+f"(c[1]), "+f"(c[2]), "+f"(c[3])
        : "r"(a0), "r"(a1), "r"(a2), "r"(a3), "r"(b0), "r"(b1));
}
__device__ __forceinline__ unsigned h2u(__half2 h) {
    return *(unsigned*)&h;
}

// ---------------- kernel 1: log0 scale -> pre-scaled fp16 field ----------------
__global__ void log0_scale_kernel(const float* __restrict__ x) {
    int pid = blockIdx.x * blockDim.x + threadIdx.x;
    int b = pid >> 16, p = pid & (PLANE - 1);
    const float* xb = x + ((size_t)b * C_IN) * PLANE + p;
    float v[C_IN], ss = 0.f;
#pragma unroll
    for (int c = 0; c < C_IN; c++) { v[c] = xb[(size_t)c << 16]; ss += v[c] * v[c]; }
    float n = fmaxf(sqrtf(ss), 1e-7f);
    float S = atanhf(fminf(0.1f * n, 1.0f - 1e-6f)) / (0.1f * n);

    __half2 h2[16];
#pragma unroll
    for (int c16 = 0; c16 < 2; c16++) {
        const float* u = v + c16 * 16;
#pragma unroll
        for (int t = 0; t < 4; t++) {
            h2[c16 * 8 + 2 * t]     = __floats2half2_rn(S * u[2 * t],     S * u[2 * t + 1]);
            h2[c16 * 8 + 2 * t + 1] = __floats2half2_rn(S * u[2 * t + 8], S * u[2 * t + 9]);
        }
    }
    uint4* go = (uint4*)(g_Uh + ((((size_t)b) << 16) + p) * 32);
    const unsigned* w = (const unsigned*)h2;
#pragma unroll
    for (int j = 0; j < 4; j++)
        go[j] = make_uint4(w[4 * j], w[4 * j + 1], w[4 * j + 2], w[4 * j + 3]);
}

// ---------------- kernel 2: fp16 m16n8k16 conv + bias + relu + exp0 ----------
__global__ __launch_bounds__(NTHREADS, 2)
void pvconv_kernel(const float* __restrict__ Wk,
                   const float* __restrict__ bias,
                   float* __restrict__ out) {
    extern __shared__ char smc[];
    float* sbias = (float*)(smc + SBIAS_OFF);

    const int tid = threadIdx.x, lane = tid & 31, warp = tid >> 5;
    const int b  = blockIdx.z;
    const int r0 = blockIdx.y * TH;
    const int c0 = blockIdx.x * TW;
    const int q = lane >> 2;      // 0..7
    const int t = lane & 3;       // 0..3

    // --- stage B fragments: [chunk 18][n8 4][lane 32] uint2 (b0,b1) ---
    for (int idx = tid; idx < 18 * 4 * 32; idx += NTHREADS) {
        int chunk = idx >> 7;
        int rem   = idx & 127;
        int n8    = rem >> 5;
        int l     = rem & 31;
        int lt = l & 3, lq = l >> 2;
        int tap = chunk >> 1, c16 = chunk & 1;
        const float* w = Wk + tap * 1024 + (n8 * 8 + lq) * 32 + c16 * 16;
        __half2 b0 = __floats2half2_rn(w[2 * lt],     w[2 * lt + 1]);
        __half2 b1 = __floats2half2_rn(w[2 * lt + 8], w[2 * lt + 9]);
        ((uint2*)(smc + SWF_OFF))[idx] = make_uint2(h2u(b0), h2u(b1));
    }
    if (tid < 32) sbias[tid] = bias[tid];

    // --- stage whole u tile (all 32 cin) via cp.async, zfill halo ---
    for (int idx = tid; idx < POS * 4; idx += NTHREADS) {
        int pos = idx >> 2, part = idx & 3;
        int irow = pos / IW, icol = pos - irow * IW;
        int grow = r0 - 1 + irow, gcol = c0 - 1 + icol;
        bool ok = ((unsigned)grow < 256u) && ((unsigned)gcol < 256u);
        const char* src = (const char*)g_Uh +
            ((((size_t)b << 16) + ((ok ? grow : 0) << 8) + (ok ? gcol : 0)) * 64) + part * 16;
        cp16(su32(smc) + pos * PBYTES + part * 16, src, ok ? 16 : 0);
    }
    asm volatile("cp.async.commit_group;" ::: "memory");
    asm volatile("cp.async.wait_group 0;" ::: "memory");
    __syncthreads();

    float acc[4][4][4];
#pragma unroll
    for (int g = 0; g < 4; g++)
#pragma unroll
        for (int n = 0; n < 4; n++)
#pragma unroll
            for (int r = 0; r < 4; r++) acc[g][n][r] = 0.f;

    // --- mainloop: 9 taps x 2 k16 chunks, fully unrolled, no barriers ---
    const char* suc = smc;
    const uint2* bb = (const uint2*)(smc + SWF_OFF) + lane;
#pragma unroll
    for (int tap = 0; tap < KTAPS; tap++) {
        const int ki = tap / 3, kj = tap - ki * 3;
        const int pbase = (warp + ki) * IW + q + kj;
#pragma unroll
        for (int c16 = 0; c16 < 2; c16++) {
            const int chunk = tap * 2 + c16;
            uint2 bfr[4];
#pragma unroll
            for (int n8 = 0; n8 < 4; n8++) bfr[n8] = bb[chunk * 128 + n8 * 32];

            const int koff = t * 8 + c16 * 32;
            uint2 lo[4], hi[4];
#pragma unroll
            for (int g = 0; g < 4; g++) {
                lo[g] = *(const uint2*)(suc + (pbase + g * 16) * PBYTES + koff);
                hi[g] = *(const uint2*)(suc + (pbase + g * 16 + 8) * PBYTES + koff);
            }
#pragma unroll
            for (int n8 = 0; n8 < 4; n8++)
#pragma unroll
                for (int g = 0; g < 4; g++)
                    mma_f16(acc[g][n8], lo[g].x, hi[g].x, lo[g].y, hi[g].y,
                            bfr[n8].x, bfr[n8].y);
        }
    }

    // bias pairs (preload before vout overlay)
    float2 bfrag[4];
#pragma unroll
    for (int n8 = 0; n8 < 4; n8++) bfrag[n8] = ((const float2*)sbias)[n8 * 4 + t];

    __syncthreads();    // all warps done with su/swf -> reuse as vout staging

    // --- epilogue: bias + relu + exp0 (4-lane butterfly over couts) ---
    float* vout = (float*)smc + warp * (C_OUT * 65);
#pragma unroll
    for (int g = 0; g < 4; g++) {
        float s0 = 0.f, s1 = 0.f;
#pragma unroll
        for (int n8 = 0; n8 < 4; n8++) {
            float2 bbv = bfrag[n8];
            float v0 = fmaxf(acc[g][n8][0] + bbv.x, 0.f);
            float v1 = fmaxf(acc[g][n8][1] + bbv.y, 0.f);
            float v2 = fmaxf(acc[g][n8][2] + bbv.x, 0.f);
            float v3 = fmaxf(acc[g][n8][3] + bbv.y, 0.f);
            s0 += v0 * v0 + v1 * v1;
            s1 += v2 * v2 + v3 * v3;
            acc[g][n8][0] = v0; acc[g][n8][1] = v1;
            acc[g][n8][2] = v2; acc[g][n8][3] = v3;
        }
        s0 += __shfl_xor_sync(0xffffffffu, s0, 1);
        s0 += __shfl_xor_sync(0xffffffffu, s0, 2);
        s1 += __shfl_xor_sync(0xffffffffu, s1, 1);
        s1 += __shfl_xor_sync(0xffffffffu, s1, 2);
        float n0 = fmaxf(sqrtf(s0), 1e-7f);
        float n1 = fmaxf(sqrtf(s1), 1e-7f);
        float f0 = tanhf(0.1f * n0) / (0.1f * n0);
        float f1 = tanhf(0.1f * n1) / (0.1f * n1);
        const int colA = g * 16 + q;
        const int colB = colA + 8;
#pragma unroll
        for (int n8 = 0; n8 < 4; n8++) {
            int cbase = n8 * 8 + 2 * t;
            vout[cbase * 65 + colA]       = f0 * acc[g][n8][0];
            vout[(cbase + 1) * 65 + colA] = f0 * acc[g][n8][1];
            vout[cbase * 65 + colB]       = f1 * acc[g][n8][2];
            vout[(cbase + 1) * 65 + colB] = f1 * acc[g][n8][3];
        }
    }
    __syncwarp();

    // --- coalesced stores: warp copies its row, all 32 couts ---
    {
        float* outb = out + (((size_t)b * C_OUT) << 16) + ((r0 + warp) << 8) + c0;
#pragma unroll 4
        for (int j = 0; j < 64; j++) {
            int c = j >> 1, half = j & 1;
            float v = vout[c * 65 + lane + (half << 5)];
            outb[((size_t)c << 16) + lane + (half << 5)] = v;
        }
    }
}

// ---------------- launch ----------------
extern "C" void kernel_launch(void* const* d_in, const int* in_sizes, int n_in,
                              void* d_out, int out_size) {
    const float* x    = (const float*)d_in[0];
    const float* Wk   = (const float*)d_in[1];
    const float* bias = (const float*)d_in[2];
    float* out = (float*)d_out;

    cudaFuncSetAttribute(pvconv_kernel,
                         cudaFuncAttributeMaxDynamicSharedMemorySize, SMEM_BYTES);

    // kernel 1: per-pixel log0 scale -> pre-scaled fp16 NHWC32 field
    log0_scale_kernel<<<(B_SZ * PLANE) / 256, 256>>>(x);

    // kernel 2: fp16 tensor-core conv + bias + relu + exp0
    dim3 grid(HW_DIM / TW, HW_DIM / TH, B_SZ);   // (4, 32, 4) = 512 blocks
    pvconv_kernel<<<grid, NTHREADS, SMEM_BYTES>>>(Wk, bias, out);
}

// round 13
// speedup vs baseline: 1.7020x; 1.1739x over previous
#include <cuda_runtime.h>
#include <cuda_fp16.h>
#include <cstdint>

// ---------------- problem constants ----------------
#define B_SZ   4
#define C_IN   32
#define C_OUT  32
#define HW_DIM 256
#define PLANE  (HW_DIM * HW_DIM)
#define KTAPS  9

// conv tile: 64 cols x 8 rows per block, 256 threads = 8 warps (1 row/warp)
#define TW 64
#define TH 8
#define IW 66
#define IH 10
#define POS (IH * IW)              // 660
#define NTHREADS 256
#define PBYTES 80                  // 64 data bytes + 16 pad (LDSM conflict-free)

#define SU_BYTES   (POS * PBYTES)          // 52800
#define SWF_OFF    SU_BYTES                // B frags: [chunk18][pair2][lane32] uint4
#define SWF_BYTES  (18 * 2 * 32 * 16)      // 18432
#define SBIAS_OFF  (SWF_OFF + SWF_BYTES)   // 71232
#define SMEM_BYTES (SBIAS_OFF + 128)       // 71360 -> 2 blocks/SM

// pre-scaled fp16 u field, NHWC32, NATURAL k order (k0..k31 consecutive)
__device__ __half g_Uh[(size_t)B_SZ * PLANE * 32];   // 16.8 MB

// ---------------- helpers ----------------
__device__ __forceinline__ unsigned su32(const void* p) {
    return (unsigned)__cvta_generic_to_shared(p);
}
__device__ __forceinline__ void cp16(unsigned d, const void* s, int sz) {
    asm volatile("cp.async.ca.shared.global [%0], [%1], 16, %2;" :: "r"(d), "l"(s), "r"(sz));
}
__device__ __forceinline__ void mma_f16(float* c, unsigned a0, unsigned a1,
                                        unsigned a2, unsigned a3,
                                        unsigned b0, unsigned b1) {
    asm("mma.sync.aligned.m16n8k16.row.col.f32.f16.f16.f32 "
        "{%0,%1,%2,%3},{%4,%5,%6,%7},{%8,%9},{%0,%1,%2,%3};"
        : "+f"(c[0]), "+f"(c[1]), "+f"(c[2]), "+f"(c[3])
        : "r"(a0), "r"(a1), "r"(a2), "r"(a3), "r"(b0), "r"(b1));
}
__device__ __forceinline__ void ldsm_x4(unsigned* a, unsigned addr) {
    asm volatile("ldmatrix.sync.aligned.m8n8.x4.shared.b16 {%0,%1,%2,%3}, [%4];"
        : "=r"(a[0]), "=r"(a[1]), "=r"(a[2]), "=r"(a[3]) : "r"(addr));
}
__device__ __forceinline__ unsigned h2u(__half2 h) { return *(unsigned*)&h; }

// ---------------- kernel 1: log0 scale -> pre-scaled fp16 field ----------------
__global__ void log0_scale_kernel(const float* __restrict__ x) {
    int pid = blockIdx.x * blockDim.x + threadIdx.x;
    int b = pid >> 16, p = pid & (PLANE - 1);
    const float* xb = x + ((size_t)b * C_IN) * PLANE + p;
    float v[C_IN], ss = 0.f;
#pragma unroll
    for (int c = 0; c < C_IN; c++) { v[c] = xb[(size_t)c << 16]; ss += v[c] * v[c]; }
    float n = fmaxf(sqrtf(ss), 1e-7f);
    float S = atanhf(fminf(0.1f * n, 1.0f - 1e-6f)) / (0.1f * n);

    unsigned w[16];
#pragma unroll
    for (int j = 0; j < 16; j++)
        w[j] = h2u(__floats2half2_rn(S * v[2 * j], S * v[2 * j + 1]));
    uint4* go = (uint4*)(g_Uh + ((((size_t)b) << 16) + p) * 32);
#pragma unroll
    for (int j = 0; j < 4; j++)
        go[j] = make_uint4(w[4 * j], w[4 * j + 1], w[4 * j + 2], w[4 * j + 3]);
}

// ---------------- kernel 2: fp16 m16n8k16 conv + bias + relu + exp0 ----------
__global__ __launch_bounds__(NTHREADS, 2)
void pvconv_kernel(const float* __restrict__ Wk,
                   const float* __restrict__ bias,
                   float* __restrict__ out) {
    extern __shared__ char smc[];
    float* sbias = (float*)(smc + SBIAS_OFF);

    const int tid = threadIdx.x, lane = tid & 31, warp = tid >> 5;
    const int b  = blockIdx.z;
    const int r0 = blockIdx.y * TH;
    const int c0 = blockIdx.x * TW;
    const int q = lane >> 2;      // 0..7
    const int t = lane & 3;       // 0..3

    // --- stage B fragments: [chunk18][pair2][lane32] uint4 = 2 n8's (b0,b1) ---
    for (int idx = tid; idx < 18 * 2 * 32; idx += NTHREADS) {
        int chunk = idx >> 6;
        int pair  = (idx >> 5) & 1;
        int l     = idx & 31;
        int lt = l & 3, lq = l >> 2;
        int tap = chunk >> 1, c16 = chunk & 1;
        const float* w0 = Wk + tap * 1024 + ((pair * 2) * 8 + lq) * 32 + c16 * 16;
        const float* w1 = w0 + 8 * 32;
        uint4 f;
        f.x = h2u(__floats2half2_rn(w0[2 * lt],     w0[2 * lt + 1]));
        f.y = h2u(__floats2half2_rn(w0[2 * lt + 8], w0[2 * lt + 9]));
        f.z = h2u(__floats2half2_rn(w1[2 * lt],     w1[2 * lt + 1]));
        f.w = h2u(__floats2half2_rn(w1[2 * lt + 8], w1[2 * lt + 9]));
        ((uint4*)(smc + SWF_OFF))[idx] = f;
    }
    if (tid < 32) sbias[tid] = bias[tid];

    // --- stage whole u tile (all 32 cin) via cp.async, zfill halo ---
    for (int idx = tid; idx < POS * 4; idx += NTHREADS) {
        int pos = idx >> 2, part = idx & 3;
        int irow = pos / IW, icol = pos - irow * IW;
        int grow = r0 - 1 + irow, gcol = c0 - 1 + icol;
        bool ok = ((unsigned)grow < 256u) && ((unsigned)gcol < 256u);
        const char* src = (const char*)g_Uh +
            ((((size_t)b << 16) + ((ok ? grow : 0) << 8) + (ok ? gcol : 0)) * 64) + part * 16;
        cp16(su32(smc) + pos * PBYTES + part * 16, src, ok ? 16 : 0);
    }
    asm volatile("cp.async.commit_group;" ::: "memory");
    asm volatile("cp.async.wait_group 0;" ::: "memory");
    __syncthreads();

    float acc[4][4][4];
#pragma unroll
    for (int g = 0; g < 4; g++)
#pragma unroll
        for (int n = 0; n < 4; n++)
#pragma unroll
            for (int r = 0; r < 4; r++) acc[g][n][r] = 0.f;

    // ldmatrix per-lane base: row = lane&15 (m within m16), kbyte = (lane>>4)*16
    const unsigned abase0 = su32(smc) + (warp * IW + (lane & 15)) * PBYTES
                            + ((lane >> 4) << 4);
    const uint4* swf4 = (const uint4*)(smc + SWF_OFF) + lane;

    // --- mainloop: 9 taps x 2 k16 chunks, fully unrolled, no barriers ---
#pragma unroll
    for (int tap = 0; tap < KTAPS; tap++) {
        const int ki = tap / 3, kj = tap - ki * 3;
        const unsigned atap = abase0 + (ki * IW + kj) * PBYTES;
#pragma unroll
        for (int c16 = 0; c16 < 2; c16++) {
            const int chunk = tap * 2 + c16;
            uint4 bf0 = swf4[chunk * 64];        // n8 0,1
            uint4 bf1 = swf4[chunk * 64 + 32];   // n8 2,3

            unsigned a[4][4];
#pragma unroll
            for (int g = 0; g < 4; g++)
                ldsm_x4(a[g], atap + g * 16 * PBYTES + c16 * 32);

#pragma unroll
            for (int g = 0; g < 4; g++) {
                mma_f16(acc[g][0], a[g][0], a[g][1], a[g][2], a[g][3], bf0.x, bf0.y);
                mma_f16(acc[g][1], a[g][0], a[g][1], a[g][2], a[g][3], bf0.z, bf0.w);
                mma_f16(acc[g][2], a[g][0], a[g][1], a[g][2], a[g][3], bf1.x, bf1.y);
                mma_f16(acc[g][3], a[g][0], a[g][1], a[g][2], a[g][3], bf1.z, bf1.w);
            }
        }
    }

    // bias pairs
    float2 bfrag[4];
#pragma unroll
    for (int n8 = 0; n8 < 4; n8++) bfrag[n8] = ((const float2*)sbias)[n8 * 4 + t];

    // --- epilogue: bias + relu + exp0 (4-lane butterfly), DIRECT stores ---
    float* outb = out + (((size_t)b * C_OUT) << 16) + ((r0 + warp) << 8) + c0;
#pragma unroll
    for (int g = 0; g < 4; g++) {
        float s0 = 0.f, s1 = 0.f;
#pragma unroll
        for (int n8 = 0; n8 < 4; n8++) {
            float2 bbv = bfrag[n8];
            float v0 = fmaxf(acc[g][n8][0] + bbv.x, 0.f);
            float v1 = fmaxf(acc[g][n8][1] + bbv.y, 0.f);
            float v2 = fmaxf(acc[g][n8][2] + bbv.x, 0.f);
            float v3 = fmaxf(acc[g][n8][3] + bbv.y, 0.f);
            s0 += v0 * v0 + v1 * v1;
            s1 += v2 * v2 + v3 * v3;
            acc[g][n8][0] = v0; acc[g][n8][1] = v1;
            acc[g][n8][2] = v2; acc[g][n8][3] = v3;
        }
        s0 += __shfl_xor_sync(0xffffffffu, s0, 1);
        s0 += __shfl_xor_sync(0xffffffffu, s0, 2);
        s1 += __shfl_xor_sync(0xffffffffu, s1, 1);
        s1 += __shfl_xor_sync(0xffffffffu, s1, 2);
        float n0 = fmaxf(sqrtf(s0), 1e-7f);
        float n1 = fmaxf(sqrtf(s1), 1e-7f);
        float f0 = tanhf(0.1f * n0) / (0.1f * n0);
        float f1 = tanhf(0.1f * n1) / (0.1f * n1);
        float* pA = outb + g * 16 + q;       // colA
        float* pB = pA + 8;                  // colB
#pragma unroll
        for (int n8 = 0; n8 < 4; n8++) {
            const size_t co0 = (size_t)(n8 * 8 + 2 * t) << 16;
            const size_t co1 = co0 + (1ull << 16);
            pA[co0] = f0 * acc[g][n8][0];
            pA[co1] = f0 * acc[g][n8][1];
            pB[co0] = f1 * acc[g][n8][2];
            pB[co1] = f1 * acc[g][n8][3];
        }
    }
}

// ---------------- launch ----------------
extern "C" void kernel_launch(void* const* d_in, const int* in_sizes, int n_in,
                              void* d_out, int out_size) {
    const float* x    = (const float*)d_in[0];
    const float* Wk   = (const float*)d_in[1];
    const float* bias = (const float*)d_in[2];
    float* out = (float*)d_out;

    cudaFuncSetAttribute(pvconv_kernel,
                         cudaFuncAttributeMaxDynamicSharedMemorySize, SMEM_BYTES);

    // kernel 1: per-pixel log0 scale -> pre-scaled fp16 NHWC32 field
    log0_scale_kernel<<<(B_SZ * PLANE) / 256, 256>>>(x);

    // kernel 2: fp16 tensor-core conv + bias + relu + exp0
    dim3 grid(HW_DIM / TW, HW_DIM / TH, B_SZ);   // (4, 32, 4) = 512 blocks
    pvconv_kernel<<<grid, NTHREADS, SMEM_BYTES>>>(Wk, bias, out);
}